// round 2
// baseline (speedup 1.0000x reference)
#include <cuda_runtime.h>
#include <cstdint>
#include <cstddef>

typedef unsigned long long u64;

// packed fp32x2 FMA: d = a*b + d (per 32-bit half). sm_100+.
#define FMA2(d, a, b) asm("fma.rn.f32x2 %0, %1, %2, %0;" : "+l"(d) : "l"(a), "l"(b))

#define GEMM16()                                                  \
    FMA2(acc[0],  xA.x, wA.x); FMA2(acc[1],  xA.y, wA.x);         \
    FMA2(acc[2],  xB.x, wA.x); FMA2(acc[3],  xB.y, wA.x);         \
    FMA2(acc[4],  xA.x, wA.y); FMA2(acc[5],  xA.y, wA.y);         \
    FMA2(acc[6],  xB.x, wA.y); FMA2(acc[7],  xB.y, wA.y);         \
    FMA2(acc[8],  xA.x, wB.x); FMA2(acc[9],  xA.y, wB.x);         \
    FMA2(acc[10], xB.x, wB.x); FMA2(acc[11], xB.y, wB.x);         \
    FMA2(acc[12], xA.x, wB.y); FMA2(acc[13], xA.y, wB.y);         \
    FMA2(acc[14], xB.x, wB.y); FMA2(acc[15], xB.y, wB.y);

constexpr int NPIX  = 256 * 256;
constexpr int HS    = 18;     // halo side
constexpr int PHALO = 324;    // 18*18
constexpr int PPAD  = 328;    // padded (mult of 8)
constexpr int NPP   = PPAD / 2;   // 164 u64 per row

// -------- device scratch (static; no allocations) --------
__device__ float g_v[8 * 64 * NPIX];          // [br*4+b][ch][n]
__device__ float g_part[256 * 5120];          // [tile][(bb*8+head)*80 + job]
__device__ float g_gr[5120];                  // reduced gram/sumsq
__device__ float g_M[8 * 64 * 64];            // [obr*4+b][row][col]

// ==================== K1: 1x1 conv + dw3x3 + gram partials + v ====================
// grid (256 tiles, 8 bb), 256 threads
constexpr int SMEM_K1 = 146688;

__global__ void __launch_bounds__(256, 1)
k1_qkv(const float* __restrict__ x,
       const float* __restrict__ wqkv1, const float* __restrict__ wqkv2,
       const float* __restrict__ wdw1,  const float* __restrict__ wdw2)
{
    extern __shared__ char sm[];
    float* xs   = (float*)(sm);               // [64][328]
    float* ys   = (float*)(sm + 83968);       // [24][328]
    u64*   ws2  = (u64*)  (sm + 115456);      // [64][24]
    float* wdws = (float*)(sm + 127744);      // [24][12]
    float* qs   = (float*)(sm + 128896);      // [8][258]
    float* ks   = (float*)(sm + 137152);      // [8][258]
    u64*   red  = (u64*)  (sm + 145408);      // [80][2]
    const u64* xs2 = (const u64*)xs;
    u64*       ys2 = (u64*)ys;

    int t    = threadIdx.x;
    int tile = blockIdx.x;
    int bb   = blockIdx.y;
    int br   = bb >> 2, b = bb & 3;
    int ty0  = (tile >> 4) << 4;
    int tx0  = (tile & 15) << 4;

    const float* wqkv = br ? wqkv2 : wqkv1;
    const float* wdw  = br ? wdw2  : wdw1;
    const float* xb   = x + ((size_t)b * 128 + (size_t)br * 64) * NPIX;

    // load halo (zero pad outside image)
    for (int idx = t; idx < 64 * PHALO; idx += 256) {
        int c = idx / PHALO, p = idx - c * PHALO;
        int hy = ty0 - 1 + p / HS;
        int hx = tx0 - 1 + (p % HS);
        float v = 0.f;
        if ((unsigned)hy < 256u && (unsigned)hx < 256u)
            v = xb[(size_t)c * NPIX + (hy << 8) + hx];
        xs[c * PPAD + p] = v;
    }
    if (t < 64) {
        xs[t * PPAD + 324] = 0.f; xs[t * PPAD + 325] = 0.f;
        xs[t * PPAD + 326] = 0.f; xs[t * PPAD + 327] = 0.f;
    }
    __syncthreads();

    for (int head = 0; head < 8; head++) {
        // stage per-head weights (24 outputs: q0-7,k0-7,v0-7 of this head)
        for (int idx = t; idx < 64 * 24; idx += 256) {
            int o = idx % 24, c = idx / 24;
            int part = o >> 3, j = o & 7;
            unsigned wb = __float_as_uint(wqkv[(part * 64 + head * 8 + j) * 64 + c]);
            ws2[c * 24 + o] = ((u64)wb << 32) | wb;
        }
        if (t < 24 * 9) {
            int o = t / 9, k9 = t - o * 9;
            int part = o >> 3, j = o & 7;
            wdws[o * 12 + k9] = wdw[(part * 64 + head * 8 + j) * 9 + k9];
        }
        __syncthreads();

        // 1x1 GEMM: ys[24][328] = W[24][64] @ xs[64][328] (f32x2)
        if (t < 246) {
            int ot = t / 41, pt = t - ot * 41;
            int o0 = ot * 4, pp0 = pt * 4;
            u64 acc[16];
            #pragma unroll
            for (int i = 0; i < 16; i++) acc[i] = 0ull;
            #pragma unroll 8
            for (int c = 0; c < 64; c++) {
                ulonglong2 wA = *(const ulonglong2*)(ws2 + c * 24 + o0);
                ulonglong2 wB = *(const ulonglong2*)(ws2 + c * 24 + o0 + 2);
                ulonglong2 xA = *(const ulonglong2*)(xs2 + c * NPP + pp0);
                ulonglong2 xB = *(const ulonglong2*)(xs2 + c * NPP + pp0 + 2);
                GEMM16();
            }
            #pragma unroll
            for (int i = 0; i < 4; i++) {
                *(ulonglong2*)(ys2 + (o0 + i) * NPP + pp0)     = make_ulonglong2(acc[i*4+0], acc[i*4+1]);
                *(ulonglong2*)(ys2 + (o0 + i) * NPP + pp0 + 2) = make_ulonglong2(acc[i*4+2], acc[i*4+3]);
            }
        }
        __syncthreads();

        // depthwise 3x3, q/k -> smem, v -> global
        {
            int py = t >> 4, px = t & 15;
            int base = py * HS + px;
            int n = ((ty0 + py) << 8) + tx0 + px;
            float* vout = g_v + ((size_t)bb * 64 + (size_t)head * 8) * NPIX + n;
            #pragma unroll
            for (int j = 0; j < 24; j++) {
                const float* yr = ys + j * PPAD + base;
                const float* wr = wdws + j * 12;
                float z = 0.f;
                #pragma unroll
                for (int dy = 0; dy < 3; dy++) {
                    z += wr[dy*3+0] * yr[dy*HS+0];
                    z += wr[dy*3+1] * yr[dy*HS+1];
                    z += wr[dy*3+2] * yr[dy*HS+2];
                }
                if (j < 8)       qs[j * 258 + t] = z;
                else if (j < 16) ks[(j - 8) * 258 + t] = z;
                else             vout[(size_t)(j - 16) * NPIX] = z;
            }
        }
        __syncthreads();

        // Gram (8x8) + sumsq(q,k): 80 jobs x 2 K-slices
        if (t < 160) {
            int job = t >> 1, slice = t & 1;
            const u64* qs2 = (const u64*)qs;   // stride 129 u64
            const u64* ks2 = (const u64*)ks;
            const u64 *pa, *pb;
            if (job < 64)      { pa = qs2 + (job >> 3) * 129; pb = ks2 + (job & 7) * 129; }
            else if (job < 72) { pa = qs2 + (job - 64) * 129; pb = pa; }
            else               { pa = ks2 + (job - 72) * 129; pb = pa; }
            pa += slice * 64; pb += slice * 64;
            u64 acc = 0ull;
            #pragma unroll 8
            for (int p = 0; p < 64; p++) { u64 av = pa[p], bv = pb[p]; FMA2(acc, av, bv); }
            red[job * 2 + slice] = acc;
        }
        __syncthreads();
        if (t < 80) {
            u64 a0 = red[t * 2], a1 = red[t * 2 + 1];
            float s = __uint_as_float((unsigned)a0) + __uint_as_float((unsigned)(a0 >> 32))
                    + __uint_as_float((unsigned)a1) + __uint_as_float((unsigned)(a1 >> 32));
            g_part[(size_t)tile * 5120 + (bb * 8 + head) * 80 + t] = s;
        }
        __syncthreads();
    }
}

// ==================== K1b: reduce partials over 256 tiles ====================
__global__ void k1b_reduce()
{
    int row = blockIdx.x * 256 + threadIdx.x;   // 5120 rows
    float s = 0.f;
    #pragma unroll 8
    for (int tile = 0; tile < 256; tile++)
        s += g_part[(size_t)tile * 5120 + row];
    g_gr[row] = s;
}

// ==================== K2: softmax + fold projection -> M ====================
__global__ void k2_attn(const float* __restrict__ wpo1, const float* __restrict__ wpo2,
                        const float* __restrict__ t1,   const float* __restrict__ t2)
{
    __shared__ float attn_s[8 * 64 * 8];   // [bb][ch=h*8+c][d]
    int t = threadIdx.x;   // 512
    {
        int c = t & 7, h = (t >> 3) & 7, bb = t >> 6;
        int br = bb >> 2;
        float tv = (br ? t2 : t1)[h];
        const float* gr = g_gr + (bb * 8 + h) * 80;
        float iq = 1.f / fmaxf(sqrtf(gr[64 + c]), 1e-12f);
        float lg[8];
        float mx = -1e30f;
        #pragma unroll
        for (int d = 0; d < 8; d++) {
            float ik = 1.f / fmaxf(sqrtf(gr[72 + d]), 1e-12f);
            float l = gr[c * 8 + d] * iq * ik * tv;
            lg[d] = l; mx = fmaxf(mx, l);
        }
        float ssum = 0.f;
        #pragma unroll
        for (int d = 0; d < 8; d++) { lg[d] = expf(lg[d] - mx); ssum += lg[d]; }
        float inv = 1.f / ssum;
        #pragma unroll
        for (int d = 0; d < 8; d++)
            attn_s[(bb * 64 + h * 8 + c) * 8 + d] = lg[d] * inv;
    }
    __syncthreads();
    // M[bb][row][j] = sum_u wpo[row][head(j)*8+u] * attn[bb][head(j)*8+u][j&7]
    for (int i = t; i < 8 * 64 * 64; i += 512) {
        int j = i & 63, row = (i >> 6) & 63, bb = i >> 12;
        const float* wpo = (bb >> 2) ? wpo2 : wpo1;
        int hj = j >> 3, jj = j & 7;
        float s = 0.f;
        #pragma unroll
        for (int u = 0; u < 8; u++)
            s += wpo[row * 64 + hj * 8 + u] * attn_s[(bb * 64 + hj * 8 + u) * 8 + jj];
        g_M[i] = s;
    }
}

// ==================== K4: out = [M1@v2 ; M2@v1] per pixel ====================
// grid (1024 chunks of 64 px, 4 batches), 256 threads
constexpr int SMEM_K4 = 98304;

__global__ void __launch_bounds__(256, 2)
k4_out(float* __restrict__ out)
{
    extern __shared__ char sm[];
    float* vs  = (float*)sm;             // [128][64] rows 0-63: v(br=1), 64-127: v(br=0)
    u64*   ms2 = (u64*)(sm + 32768);     // [64][128] duplicated pairs
    const u64* vs2 = (const u64*)vs;     // [128][32]

    int t  = threadIdx.x;
    int b  = blockIdx.y;
    int n0 = blockIdx.x * 64;

    for (int idx = t; idx < 128 * 16; idx += 256) {
        int c = idx >> 4, pv = idx & 15;
        int srcbr = (c < 64) ? 1 : 0;
        int ch = c & 63;
        float4 v4 = *(const float4*)(g_v + ((size_t)(srcbr * 4 + b) * 64 + ch) * NPIX + n0 + pv * 4);
        *(float4*)(vs + c * 64 + pv * 4) = v4;
    }
    for (int idx = t; idx < 64 * 128; idx += 256) {
        int c = idx >> 7, o = idx & 127;
        int obr = o >> 6, row = o & 63;
        unsigned mb = __float_as_uint(g_M[((obr * 4 + b) * 64 + row) * 64 + c]);
        ms2[c * 128 + o] = ((u64)mb << 32) | mb;
    }
    __syncthreads();

    int ot = t >> 3, pt = t & 7;
    int o0 = ot * 4, pp0 = pt * 4;     // o0 in [0,128), pairs pp0 in [0,32)
    int vbase = (o0 < 64) ? 0 : 64;
    u64 acc[16];
    #pragma unroll
    for (int i = 0; i < 16; i++) acc[i] = 0ull;
    #pragma unroll 8
    for (int c = 0; c < 64; c++) {
        ulonglong2 wA = *(const ulonglong2*)(ms2 + c * 128 + o0);
        ulonglong2 wB = *(const ulonglong2*)(ms2 + c * 128 + o0 + 2);
        ulonglong2 xA = *(const ulonglong2*)(vs2 + (vbase + c) * 32 + pp0);
        ulonglong2 xB = *(const ulonglong2*)(vs2 + (vbase + c) * 32 + pp0 + 2);
        GEMM16();
    }
    #pragma unroll
    for (int i = 0; i < 4; i++) {
        float* outp = out + ((size_t)b * 128 + o0 + i) * NPIX + n0 + pp0 * 2;
        *(ulonglong2*)outp       = make_ulonglong2(acc[i*4+0], acc[i*4+1]);
        *(ulonglong2*)(outp + 4) = make_ulonglong2(acc[i*4+2], acc[i*4+3]);
    }
}

// ==================== launch ====================
extern "C" void kernel_launch(void* const* d_in, const int* in_sizes, int n_in,
                              void* d_out, int out_size)
{
    const float* x     = (const float*)d_in[0];
    const float* wqkv1 = (const float*)d_in[1];
    const float* wqkv2 = (const float*)d_in[2];
    const float* wdw1  = (const float*)d_in[3];
    const float* wdw2  = (const float*)d_in[4];
    const float* wpo1  = (const float*)d_in[5];
    const float* wpo2  = (const float*)d_in[6];
    const float* t1    = (const float*)d_in[7];
    const float* t2    = (const float*)d_in[8];
    float* out = (float*)d_out;

    cudaFuncSetAttribute(k1_qkv, cudaFuncAttributeMaxDynamicSharedMemorySize, SMEM_K1);
    cudaFuncSetAttribute(k4_out, cudaFuncAttributeMaxDynamicSharedMemorySize, SMEM_K4);

    k1_qkv<<<dim3(256, 8), 256, SMEM_K1>>>(x, wqkv1, wqkv2, wdw1, wdw2);
    k1b_reduce<<<20, 256>>>();
    k2_attn<<<1, 512>>>(wpo1, wpo2, t1, t2);
    k4_out<<<dim3(1024, 4), 256, SMEM_K4>>>(out);
}

// round 3
// speedup vs baseline: 1.4226x; 1.4226x over previous
#include <cuda_runtime.h>
#include <cstdint>
#include <cstddef>

typedef unsigned long long u64;

// packed fp32x2 FMA: d = a*b + d (per 32-bit half). sm_100+.
#define FMA2(d, a, b) asm("fma.rn.f32x2 %0, %1, %2, %0;" : "+l"(d) : "l"(a), "l"(b))

__device__ __forceinline__ u64 pack2(float a, float b) {
    u64 r; asm("mov.b64 %0, {%1, %2};" : "=l"(r) : "f"(a), "f"(b)); return r;
}
__device__ __forceinline__ u64 dup2(float a) {
    u64 r; asm("mov.b64 %0, {%1, %1};" : "=l"(r) : "f"(a)); return r;
}
__device__ __forceinline__ void unpack2(u64 v, float& a, float& b) {
    asm("mov.b64 {%0, %1}, %2;" : "=f"(a), "=f"(b) : "l"(v));
}

constexpr int NPIX  = 256 * 256;
constexpr int HS    = 18;     // halo side
constexpr int PHALO = 324;    // 18*18
constexpr int PPAD  = 384;    // padded pixel count (192 pairs = 6 warp-iters)
constexpr int NPR   = 192;    // u64 pairs per channel row

// -------- device scratch (static; no allocations) --------
__device__ float g_v[8 * 64 * NPIX];          // [br*4+b][ch][n]
__device__ float g_part[256 * 5120];          // [tile][(bb*8+head)*80 + job]
__device__ float g_gr[5120];
__device__ float g_M[8 * 64 * 64];            // [obr*4+b][row][col]

// ==================== K1: 1x1 conv + dw3x3 + gram partials + v ====================
// grid (256 tiles, 8 bb), 256 threads
// smem: xs f32[64][384] @0 (98304) | ysp u64[12][384] @98304 (36864)
//       ws f32[64][24] @135168 (6144) | wdwp u64[12][12] @141312 (1152->pad 1024? use 1152)
//       qs f32[8][264] @142464 (8448) | ks @150912 (8448) | red u64[160] @159360 (1280)
constexpr int SMEM_K1 = 160640;

__global__ void __launch_bounds__(256, 1)
k1_qkv(const float* __restrict__ x,
       const float* __restrict__ wqkv1, const float* __restrict__ wqkv2,
       const float* __restrict__ wdw1,  const float* __restrict__ wdw2)
{
    extern __shared__ char sm[];
    float* xs   = (float*)(sm);               // [64][384]
    const u64* xs2 = (const u64*)sm;          // [64][192]
    u64*   ysp  = (u64*)  (sm + 98304);       // [12][384] (ch-pair, px)
    float* ws   = (float*)(sm + 135168);      // [64][24]
    u64*   wdwp = (u64*)  (sm + 141312);      // [12][12] (9 used)
    float* qs   = (float*)(sm + 142464);      // [8][264]
    float* ks   = (float*)(sm + 150912);      // [8][264]
    u64*   red  = (u64*)  (sm + 159360);      // [80][2]

    int t    = threadIdx.x;
    int tile = blockIdx.x;
    int bb   = blockIdx.y;
    int br   = bb >> 2, b = bb & 3;
    int ty0  = (tile >> 4) << 4;
    int tx0  = (tile & 15) << 4;

    const float* wqkv = br ? wqkv2 : wqkv1;
    const float* wdw  = br ? wdw2  : wdw1;
    const float* xb   = x + ((size_t)b * 128 + (size_t)br * 64) * NPIX;

    // zero pad tail cols 324..383
    for (int idx = t; idx < 64 * 60; idx += 256) {
        int c = idx / 60, p = 324 + idx - c * 60;
        xs[c * PPAD + p] = 0.f;
    }
    // load halo (zero pad outside image)
    for (int idx = t; idx < 64 * PHALO; idx += 256) {
        int c = idx / PHALO, p = idx - c * PHALO;
        int hy = ty0 - 1 + p / HS;
        int hx = tx0 - 1 + (p % HS);
        float v = 0.f;
        if ((unsigned)hy < 256u && (unsigned)hx < 256u)
            v = xb[(size_t)c * NPIX + (hy << 8) + hx];
        xs[c * PPAD + p] = v;
    }
    __syncthreads();

    for (int head = 0; head < 8; head++) {
        // ---- stage per-head weights ----
        for (int idx = t; idx < 64 * 24; idx += 256) {
            int o = idx % 24, c = idx / 24;
            int part = o >> 3, j = o & 7;
            ws[c * 24 + o] = wqkv[(part * 64 + head * 8 + j) * 64 + c];
        }
        if (t < 108) {
            int m = t / 9, k9 = t - m * 9;
            int c0 = 2 * m, c1 = 2 * m + 1;
            float w0 = wdw[((c0 >> 3) * 64 + head * 8 + (c0 & 7)) * 9 + k9];
            float w1 = wdw[((c1 >> 3) * 64 + head * 8 + (c1 & 7)) * 9 + k9];
            wdwp[m * 12 + k9] = pack2(w0, w1);
        }
        __syncthreads();

        // ---- 1x1 GEMM: 6 rows x 3 pixel-pair groups per thread ----
        {
            int w = t >> 5, lane = t & 31;
            int r0 = (w & 3) * 6;
            int pbase = (w >> 2) * 96 + lane;
            u64 acc[6][3];
            #pragma unroll
            for (int i = 0; i < 6; i++)
                #pragma unroll
                for (int j = 0; j < 3; j++) acc[i][j] = 0ull;
            #pragma unroll 4
            for (int c = 0; c < 64; c++) {
                u64 xv0 = xs2[c * NPR + pbase];
                u64 xv1 = xs2[c * NPR + pbase + 32];
                u64 xv2 = xs2[c * NPR + pbase + 64];
                const float* wc = ws + c * 24 + r0;
                #pragma unroll
                for (int i = 0; i < 6; i++) {
                    u64 wd = dup2(wc[i]);
                    FMA2(acc[i][0], wd, xv0);
                    FMA2(acc[i][1], wd, xv1);
                    FMA2(acc[i][2], wd, xv2);
                }
            }
            // write interleaved channel pairs
            #pragma unroll
            for (int a = 0; a < 3; a++) {
                int m = (r0 >> 1) + a;
                #pragma unroll
                for (int j = 0; j < 3; j++) {
                    float e0, e1, o0, o1;
                    unpack2(acc[2 * a][j],     e0, o0);   // row r0+2a: (px even, px odd)
                    unpack2(acc[2 * a + 1][j], e1, o1);   // row r0+2a+1
                    int pp = pbase + 32 * j;
                    ysp[m * PPAD + 2 * pp]     = pack2(e0, e1);
                    ysp[m * PPAD + 2 * pp + 1] = pack2(o0, o1);
                }
            }
        }
        __syncthreads();

        // ---- depthwise 3x3 on channel pairs ----
        {
            int py = t >> 4, px = t & 15;
            int base = py * HS + px;
            int n = ((ty0 + py) << 8) + tx0 + px;
            float* vout = g_v + ((size_t)bb * 64 + (size_t)head * 8) * NPIX + n;
            #pragma unroll
            for (int m = 0; m < 12; m++) {
                const u64* yr = ysp + m * PPAD + base;
                const u64* wr = wdwp + m * 12;
                u64 z = 0ull;
                FMA2(z, wr[0], yr[0]);  FMA2(z, wr[1], yr[1]);  FMA2(z, wr[2], yr[2]);
                FMA2(z, wr[3], yr[18]); FMA2(z, wr[4], yr[19]); FMA2(z, wr[5], yr[20]);
                FMA2(z, wr[6], yr[36]); FMA2(z, wr[7], yr[37]); FMA2(z, wr[8], yr[38]);
                float z0, z1; unpack2(z, z0, z1);
                int ch = 2 * m;
                if (m < 4)      { qs[ch * 264 + t] = z0;        qs[(ch + 1) * 264 + t] = z1; }
                else if (m < 8) { ks[(ch - 8) * 264 + t] = z0;  ks[(ch - 7) * 264 + t] = z1; }
                else            { vout[(size_t)(ch - 16) * NPIX] = z0;
                                  vout[(size_t)(ch - 15) * NPIX] = z1; }
            }
        }
        __syncthreads();

        // ---- Gram (8x8) + sumsq(q,k): 80 jobs x 2 interleaved K-slices ----
        if (t < 160) {
            int job = t >> 1, slice = t & 1;
            const u64* qs2 = (const u64*)qs;   // row stride 132 u64
            const u64* ks2 = (const u64*)ks;
            const u64 *pa, *pb;
            if (job < 64)      { pa = qs2 + (job >> 3) * 132; pb = ks2 + (job & 7) * 132; }
            else if (job < 72) { pa = qs2 + (job - 64) * 132; pb = pa; }
            else               { pa = ks2 + (job - 72) * 132; pb = pa; }
            u64 acc = 0ull;
            #pragma unroll 8
            for (int p = 0; p < 64; p++) {
                u64 av = pa[2 * p + slice], bv = pb[2 * p + slice];
                FMA2(acc, av, bv);
            }
            red[job * 2 + slice] = acc;
        }
        __syncthreads();
        if (t < 80) {
            float a0, a1, b0, b1;
            unpack2(red[t * 2], a0, a1);
            unpack2(red[t * 2 + 1], b0, b1);
            g_part[(size_t)tile * 5120 + (bb * 8 + head) * 80 + t] = a0 + a1 + b0 + b1;
        }
        __syncthreads();
    }
}

// ==================== K1b: reduce partials over 256 tiles ====================
__global__ void k1b_reduce()
{
    int row = blockIdx.x * 256 + threadIdx.x;   // 5120 rows
    float s = 0.f;
    #pragma unroll 8
    for (int tile = 0; tile < 256; tile++)
        s += g_part[(size_t)tile * 5120 + row];
    g_gr[row] = s;
}

// ==================== K2: softmax + fold projection -> M ====================
__global__ void k2_attn(const float* __restrict__ wpo1, const float* __restrict__ wpo2,
                        const float* __restrict__ t1,   const float* __restrict__ t2)
{
    __shared__ float attn_s[8 * 64 * 8];   // [bb][ch=h*8+c][d]
    int t = threadIdx.x;   // 512
    {
        int c = t & 7, h = (t >> 3) & 7, bb = t >> 6;
        int br = bb >> 2;
        float tv = (br ? t2 : t1)[h];
        const float* gr = g_gr + (bb * 8 + h) * 80;
        float iq = 1.f / fmaxf(sqrtf(gr[64 + c]), 1e-12f);
        float lg[8];
        float mx = -1e30f;
        #pragma unroll
        for (int d = 0; d < 8; d++) {
            float ik = 1.f / fmaxf(sqrtf(gr[72 + d]), 1e-12f);
            float l = gr[c * 8 + d] * iq * ik * tv;
            lg[d] = l; mx = fmaxf(mx, l);
        }
        float ssum = 0.f;
        #pragma unroll
        for (int d = 0; d < 8; d++) { lg[d] = expf(lg[d] - mx); ssum += lg[d]; }
        float inv = 1.f / ssum;
        #pragma unroll
        for (int d = 0; d < 8; d++)
            attn_s[(bb * 64 + h * 8 + c) * 8 + d] = lg[d] * inv;
    }
    __syncthreads();
    for (int i = t; i < 8 * 64 * 64; i += 512) {
        int j = i & 63, row = (i >> 6) & 63, bb = i >> 12;
        const float* wpo = (bb >> 2) ? wpo2 : wpo1;
        int hj = j >> 3, jj = j & 7;
        float s = 0.f;
        #pragma unroll
        for (int u = 0; u < 8; u++)
            s += wpo[row * 64 + hj * 8 + u] * attn_s[(bb * 64 + hj * 8 + u) * 8 + jj];
        g_M[i] = s;
    }
}

// ==================== K4: out = [M1@v2 ; M2@v1] per pixel ====================
// grid (512 chunks of 128 px, 4 batches), 256 threads
// smem: vs u64[128][64] @0 (64KB) | ms f32[64][128] @65536 (32KB)
constexpr int SMEM_K4 = 98304;

__global__ void __launch_bounds__(256, 2)
k4_out(float* __restrict__ out)
{
    extern __shared__ char sm[];
    u64*   vs = (u64*)sm;                // [128 rows][64 px-pairs]; rows 0-63: v(br=1), 64-127: v(br=0)
    float* ms = (float*)(sm + 65536);    // [64 c][128 o]

    int t  = threadIdx.x;
    int b  = blockIdx.y;
    int n0 = blockIdx.x * 128;

    // load v: 128 rows x 64 u64 (as ulonglong2)
    for (int idx = t; idx < 128 * 32; idx += 256) {
        int row = idx >> 5, q = idx & 31;
        int srcbb = (row < 64) ? (4 + b) : b;
        int ch = row & 63;
        ulonglong2 v2 = *(const ulonglong2*)(g_v + ((size_t)srcbb * 64 + ch) * NPIX + n0 + q * 4);
        *(ulonglong2*)(vs + row * 64 + q * 2) = v2;
    }
    // load M scalar: ms[c][o]
    for (int idx = t; idx < 64 * 128; idx += 256) {
        int c = idx >> 7, o = idx & 127;
        int obr = o >> 6;
        ms[c * 128 + o] = g_M[((obr * 4 + b) * 64 + (o & 63)) * 64 + c];
    }
    __syncthreads();

    int rowg = t >> 4, pt = t & 15;     // 16 row-groups of 8, 16 pixel-pair slots
    int r0 = rowg * 8;
    int vro = (r0 < 64) ? 0 : 64;
    u64 acc[8][4];
    #pragma unroll
    for (int i = 0; i < 8; i++)
        #pragma unroll
        for (int j = 0; j < 4; j++) acc[i][j] = 0ull;

    #pragma unroll 4
    for (int c = 0; c < 64; c++) {
        const u64* vr = vs + (vro + c) * 64 + pt;
        u64 xv0 = vr[0], xv1 = vr[16], xv2 = vr[32], xv3 = vr[48];
        const float* mc = ms + c * 128 + r0;
        #pragma unroll
        for (int i = 0; i < 8; i++) {
            u64 wd = dup2(mc[i]);
            FMA2(acc[i][0], wd, xv0);
            FMA2(acc[i][1], wd, xv1);
            FMA2(acc[i][2], wd, xv2);
            FMA2(acc[i][3], wd, xv3);
        }
    }
    #pragma unroll
    for (int i = 0; i < 8; i++) {
        float* orow = out + ((size_t)b * 128 + r0 + i) * NPIX + n0;
        #pragma unroll
        for (int j = 0; j < 4; j++)
            *(u64*)(orow + 2 * (pt + 16 * j)) = acc[i][j];
    }
}

// ==================== launch ====================
extern "C" void kernel_launch(void* const* d_in, const int* in_sizes, int n_in,
                              void* d_out, int out_size)
{
    const float* x     = (const float*)d_in[0];
    const float* wqkv1 = (const float*)d_in[1];
    const float* wqkv2 = (const float*)d_in[2];
    const float* wdw1  = (const float*)d_in[3];
    const float* wdw2  = (const float*)d_in[4];
    const float* wpo1  = (const float*)d_in[5];
    const float* wpo2  = (const float*)d_in[6];
    const float* t1    = (const float*)d_in[7];
    const float* t2    = (const float*)d_in[8];
    float* out = (float*)d_out;

    cudaFuncSetAttribute(k1_qkv, cudaFuncAttributeMaxDynamicSharedMemorySize, SMEM_K1);
    cudaFuncSetAttribute(k4_out, cudaFuncAttributeMaxDynamicSharedMemorySize, SMEM_K4);

    k1_qkv<<<dim3(256, 8), 256, SMEM_K1>>>(x, wqkv1, wqkv2, wdw1, wdw2);
    k1b_reduce<<<20, 256>>>();
    k2_attn<<<1, 512>>>(wpo1, wpo2, t1, t2);
    k4_out<<<dim3(512, 4), 256, SMEM_K4>>>(out);
}

// round 4
// speedup vs baseline: 1.5730x; 1.1057x over previous
#include <cuda_runtime.h>
#include <cstdint>
#include <cstddef>

typedef unsigned long long u64;

// packed fp32x2 FMA: d = a*b + d (per 32-bit half). sm_100+.
#define FMA2(d, a, b) asm("fma.rn.f32x2 %0, %1, %2, %0;" : "+l"(d) : "l"(a), "l"(b))

__device__ __forceinline__ u64 pack2(float a, float b) {
    u64 r; asm("mov.b64 %0, {%1, %2};" : "=l"(r) : "f"(a), "f"(b)); return r;
}
__device__ __forceinline__ u64 dup2(float a) {
    u64 r; asm("mov.b64 %0, {%1, %1};" : "=l"(r) : "f"(a)); return r;
}
__device__ __forceinline__ void unpack2(u64 v, float& a, float& b) {
    asm("mov.b64 {%0, %1}, %2;" : "=f"(a), "=f"(b) : "l"(v));
}

constexpr int NPIX  = 256 * 256;
constexpr int HS    = 18;     // halo side
constexpr int PHALO = 324;    // 18*18
constexpr int PPAD  = 384;    // padded pixel count
constexpr int NPR   = 192;    // u64 pairs per channel row
constexpr int QSTR  = 268;    // qs/ks float row stride (134 u64; 12r mod 32 distinct)

// -------- device scratch (static; no allocations) --------
__device__ float g_v[8 * 64 * NPIX];
__device__ float g_part[256 * 5120];
__device__ float g_gr[5120];
__device__ float g_M[8 * 64 * 64];

// ==================== K1: 1x1 conv + dw3x3 + gram partials + v ====================
// grid (256 tiles, 8 bb), 256 threads
// smem: xs f32[64][384]@0 | ysp u64[12][384]@98304 | wsg f32[4][64][8]@135168
//       wdwp u64[12][12]@143360 | qs f32[8][268]@144512 | ks@153088 | red u64[160]@161664
constexpr int SMEM_K1 = 162944;

__global__ void __launch_bounds__(256, 1)
k1_qkv(const float* __restrict__ x,
       const float* __restrict__ wqkv1, const float* __restrict__ wqkv2,
       const float* __restrict__ wdw1,  const float* __restrict__ wdw2)
{
    extern __shared__ char sm[];
    float* xs   = (float*)(sm);               // [64][384]
    const u64* xs2 = (const u64*)sm;          // [64][192]
    u64*   ysp  = (u64*)  (sm + 98304);       // [12][384]
    float* wsg  = (float*)(sm + 135168);      // [4][64][8]
    u64*   wdwp = (u64*)  (sm + 143360);      // [12][12]
    float* qs   = (float*)(sm + 144512);      // [8][268]
    float* ks   = (float*)(sm + 153088);      // [8][268]
    u64*   red  = (u64*)  (sm + 161664);      // [80][2]

    int t    = threadIdx.x;
    int tile = blockIdx.x;
    int bb   = blockIdx.y;
    int br   = bb >> 2, b = bb & 3;
    int ty0  = (tile >> 4) << 4;
    int tx0  = (tile & 15) << 4;

    const float* wqkv = br ? wqkv2 : wqkv1;
    const float* wdw  = br ? wdw2  : wdw1;
    const float* xb   = x + ((size_t)b * 128 + (size_t)br * 64) * NPIX;

    // zero pad tail cols 324..383
    for (int idx = t; idx < 64 * 60; idx += 256) {
        int c = idx / 60, p = 324 + idx - c * 60;
        xs[c * PPAD + p] = 0.f;
    }
    // load halo (zero pad outside image)
    for (int idx = t; idx < 64 * PHALO; idx += 256) {
        int c = idx / PHALO, p = idx - c * PHALO;
        int hy = ty0 - 1 + p / HS;
        int hx = tx0 - 1 + (p % HS);
        float v = 0.f;
        if ((unsigned)hy < 256u && (unsigned)hx < 256u)
            v = xb[(size_t)c * NPIX + (hy << 8) + hx];
        xs[c * PPAD + p] = v;
    }
    __syncthreads();

    for (int head = 0; head < 8; head++) {
        // ---- stage per-head weights ----
        for (int idx = t; idx < 64 * 24; idx += 256) {
            int o = idx % 24, c = idx / 24;
            int part = o >> 3, j = o & 7;
            int g = o / 6, slot = o - 6 * g;
            wsg[(g * 64 + c) * 8 + slot] = wqkv[(part * 64 + head * 8 + j) * 64 + c];
        }
        if (t < 108) {
            int m = t / 9, k9 = t - m * 9;
            int c0 = 2 * m, c1 = 2 * m + 1;
            float w0 = wdw[((c0 >> 3) * 64 + head * 8 + (c0 & 7)) * 9 + k9];
            float w1 = wdw[((c1 >> 3) * 64 + head * 8 + (c1 & 7)) * 9 + k9];
            wdwp[m * 12 + k9] = pack2(w0, w1);
        }
        __syncthreads();

        // ---- 1x1 GEMM: 6 rows x 3 pixel-pair groups per thread, sw pipelined ----
        {
            int w = t >> 5, lane = t & 31;
            int g = w & 3;                       // rows 6g..6g+5
            int pbase = (w >> 2) * 96 + lane;
            const float* wg = wsg + g * 512;
            u64 acc[6][3];
            #pragma unroll
            for (int i = 0; i < 6; i++)
                #pragma unroll
                for (int j = 0; j < 3; j++) acc[i][j] = 0ull;

            u64 xv0 = xs2[pbase], xv1 = xs2[pbase + 32], xv2 = xs2[pbase + 64];
            float4 wa = *(const float4*)(wg);
            float2 wb = *(const float2*)(wg + 4);
            #pragma unroll 4
            for (int c = 0; c < 64; c++) {
                u64 nx0 = xv0, nx1 = xv1, nx2 = xv2;
                float4 na = wa; float2 nb = wb;
                if (c < 63) {
                    const u64* xr = xs2 + (c + 1) * NPR + pbase;
                    nx0 = xr[0]; nx1 = xr[32]; nx2 = xr[64];
                    na = *(const float4*)(wg + (c + 1) * 8);
                    nb = *(const float2*)(wg + (c + 1) * 8 + 4);
                }
                u64 w0 = dup2(wa.x), w1 = dup2(wa.y), w2 = dup2(wa.z);
                u64 w3 = dup2(wa.w), w4 = dup2(wb.x), w5 = dup2(wb.y);
                FMA2(acc[0][0], w0, xv0); FMA2(acc[0][1], w0, xv1); FMA2(acc[0][2], w0, xv2);
                FMA2(acc[1][0], w1, xv0); FMA2(acc[1][1], w1, xv1); FMA2(acc[1][2], w1, xv2);
                FMA2(acc[2][0], w2, xv0); FMA2(acc[2][1], w2, xv1); FMA2(acc[2][2], w2, xv2);
                FMA2(acc[3][0], w3, xv0); FMA2(acc[3][1], w3, xv1); FMA2(acc[3][2], w3, xv2);
                FMA2(acc[4][0], w4, xv0); FMA2(acc[4][1], w4, xv1); FMA2(acc[4][2], w4, xv2);
                FMA2(acc[5][0], w5, xv0); FMA2(acc[5][1], w5, xv1); FMA2(acc[5][2], w5, xv2);
                xv0 = nx0; xv1 = nx1; xv2 = nx2; wa = na; wb = nb;
            }
            int r0 = 6 * g;
            #pragma unroll
            for (int a = 0; a < 3; a++) {
                int m = (r0 >> 1) + a;
                #pragma unroll
                for (int j = 0; j < 3; j++) {
                    float e0, e1, o0, o1;
                    unpack2(acc[2 * a][j],     e0, o0);
                    unpack2(acc[2 * a + 1][j], e1, o1);
                    int pp = pbase + 32 * j;
                    ysp[m * PPAD + 2 * pp]     = pack2(e0, e1);
                    ysp[m * PPAD + 2 * pp + 1] = pack2(o0, o1);
                }
            }
        }
        __syncthreads();

        // ---- depthwise 3x3, vertical strip of 4 outputs per thread ----
        {
            int pyq = t >> 6;            // 0..3
            int mp  = (t >> 4) & 3;      // 0..3
            int px  = t & 15;
            int py0 = pyq * 4;
            #pragma unroll
            for (int it = 0; it < 3; it++) {
                int m = it * 4 + mp;
                const u64* yb = ysp + m * PPAD + py0 * HS + px;
                u64 Y[6][3];
                #pragma unroll
                for (int r = 0; r < 6; r++) {
                    Y[r][0] = yb[r * HS];
                    Y[r][1] = yb[r * HS + 1];
                    Y[r][2] = yb[r * HS + 2];
                }
                const u64* wr = wdwp + m * 12;
                u64 w0 = wr[0], w1 = wr[1], w2 = wr[2];
                u64 w3 = wr[3], w4 = wr[4], w5 = wr[5];
                u64 w6 = wr[6], w7 = wr[7], w8 = wr[8];
                int ch = 2 * m;
                #pragma unroll
                for (int j = 0; j < 4; j++) {
                    u64 z = 0ull;
                    FMA2(z, w0, Y[j][0]);     FMA2(z, w1, Y[j][1]);     FMA2(z, w2, Y[j][2]);
                    FMA2(z, w3, Y[j + 1][0]); FMA2(z, w4, Y[j + 1][1]); FMA2(z, w5, Y[j + 1][2]);
                    FMA2(z, w6, Y[j + 2][0]); FMA2(z, w7, Y[j + 2][1]); FMA2(z, w8, Y[j + 2][2]);
                    float z0, z1; unpack2(z, z0, z1);
                    int tp = (py0 + j) * 16 + px;
                    if (m < 4) {
                        qs[ch * QSTR + tp] = z0; qs[(ch + 1) * QSTR + tp] = z1;
                    } else if (m < 8) {
                        ks[(ch - 8) * QSTR + tp] = z0; ks[(ch - 7) * QSTR + tp] = z1;
                    } else {
                        size_t n = (size_t)((ty0 + py0 + j) << 8) + tx0 + px;
                        float* vout = g_v + ((size_t)bb * 64 + (size_t)head * 8 + (ch - 16)) * NPIX + n;
                        vout[0] = z0; vout[NPIX] = z1;
                    }
                }
            }
        }
        __syncthreads();

        // ---- Gram (8x8) + sumsq(q,k): 80 jobs x 2 interleaved K-slices ----
        if (t < 160) {
            int job = t >> 1, slice = t & 1;
            const u64* qs2 = (const u64*)qs;   // row stride 134 u64
            const u64* ks2 = (const u64*)ks;
            const u64 *pa, *pb;
            if (job < 64)      { pa = qs2 + (job >> 3) * 134; pb = ks2 + (job & 7) * 134; }
            else if (job < 72) { pa = qs2 + (job - 64) * 134; pb = pa; }
            else               { pa = ks2 + (job - 72) * 134; pb = pa; }
            u64 acc = 0ull;
            #pragma unroll 8
            for (int p = 0; p < 64; p++) {
                u64 av = pa[2 * p + slice], bv = pb[2 * p + slice];
                FMA2(acc, av, bv);
            }
            red[job * 2 + slice] = acc;
        }
        __syncthreads();
        if (t < 80) {
            float a0, a1, b0, b1;
            unpack2(red[t * 2], a0, a1);
            unpack2(red[t * 2 + 1], b0, b1);
            g_part[(size_t)tile * 5120 + (bb * 8 + head) * 80 + t] = a0 + a1 + b0 + b1;
        }
        __syncthreads();
    }
}

// ==================== K1b: reduce partials over 256 tiles ====================
__global__ void k1b_reduce()
{
    int row = blockIdx.x * 256 + threadIdx.x;
    float s = 0.f;
    #pragma unroll 8
    for (int tile = 0; tile < 256; tile++)
        s += g_part[(size_t)tile * 5120 + row];
    g_gr[row] = s;
}

// ==================== K2: softmax + fold projection -> M ====================
__global__ void k2_attn(const float* __restrict__ wpo1, const float* __restrict__ wpo2,
                        const float* __restrict__ t1,   const float* __restrict__ t2)
{
    __shared__ float attn_s[8 * 64 * 8];
    int t = threadIdx.x;   // 512
    {
        int c = t & 7, h = (t >> 3) & 7, bb = t >> 6;
        int br = bb >> 2;
        float tv = (br ? t2 : t1)[h];
        const float* gr = g_gr + (bb * 8 + h) * 80;
        float iq = 1.f / fmaxf(sqrtf(gr[64 + c]), 1e-12f);
        float lg[8];
        float mx = -1e30f;
        #pragma unroll
        for (int d = 0; d < 8; d++) {
            float ik = 1.f / fmaxf(sqrtf(gr[72 + d]), 1e-12f);
            float l = gr[c * 8 + d] * iq * ik * tv;
            lg[d] = l; mx = fmaxf(mx, l);
        }
        float ssum = 0.f;
        #pragma unroll
        for (int d = 0; d < 8; d++) { lg[d] = expf(lg[d] - mx); ssum += lg[d]; }
        float inv = 1.f / ssum;
        #pragma unroll
        for (int d = 0; d < 8; d++)
            attn_s[(bb * 64 + h * 8 + c) * 8 + d] = lg[d] * inv;
    }
    __syncthreads();
    for (int i = t; i < 8 * 64 * 64; i += 512) {
        int j = i & 63, row = (i >> 6) & 63, bb = i >> 12;
        const float* wpo = (bb >> 2) ? wpo2 : wpo1;
        int hj = j >> 3, jj = j & 7;
        float s = 0.f;
        #pragma unroll
        for (int u = 0; u < 8; u++)
            s += wpo[row * 64 + hj * 8 + u] * attn_s[(bb * 64 + hj * 8 + u) * 8 + jj];
        g_M[i] = s;
    }
}

// ==================== K4: out = [M1@v2 ; M2@v1] per pixel ====================
// grid (512 chunks of 128 px, 4 batches), 512 threads, 2 blocks/SM
// smem: vs u64[128][64]@0 (64KB) | ms f32[64][128]@65536 (32KB)
constexpr int SMEM_K4 = 98304;

__global__ void __launch_bounds__(512, 2)
k4_out(float* __restrict__ out)
{
    extern __shared__ char sm[];
    u64*   vs = (u64*)sm;                // [128][64]; rows 0-63: v(br=1), 64-127: v(br=0)
    float* ms = (float*)(sm + 65536);    // [64 c][128 o]

    int t  = threadIdx.x;
    int b  = blockIdx.y;
    int n0 = blockIdx.x * 128;

    for (int idx = t; idx < 128 * 32; idx += 512) {
        int row = idx >> 5, q = idx & 31;
        int srcbb = (row < 64) ? (4 + b) : b;
        ulonglong2 v2 = *(const ulonglong2*)(g_v + ((size_t)srcbb * 64 + (row & 63)) * NPIX + n0 + q * 4);
        *(ulonglong2*)(vs + row * 64 + q * 2) = v2;
    }
    for (int idx = t; idx < 64 * 128; idx += 512) {
        int c = idx >> 7, o = idx & 127;
        ms[c * 128 + o] = g_M[(((o >> 6) * 4 + b) * 64 + (o & 63)) * 64 + c];
    }
    __syncthreads();

    int w = t >> 5, lane = t & 31;
    int r0 = w * 8;
    int vro = (r0 < 64) ? 0 : 64;
    u64 acc[8][2];
    #pragma unroll
    for (int i = 0; i < 8; i++) { acc[i][0] = 0ull; acc[i][1] = 0ull; }

    u64 xv0 = vs[vro * 64 + lane], xv1 = vs[vro * 64 + lane + 32];
    float4 ma = *(const float4*)(ms + r0);
    float4 mb = *(const float4*)(ms + r0 + 4);
    #pragma unroll 4
    for (int c = 0; c < 64; c++) {
        u64 nx0 = xv0, nx1 = xv1; float4 na = ma, nb = mb;
        if (c < 63) {
            const u64* vr = vs + (vro + c + 1) * 64 + lane;
            nx0 = vr[0]; nx1 = vr[32];
            const float* mc = ms + (c + 1) * 128 + r0;
            na = *(const float4*)(mc);
            nb = *(const float4*)(mc + 4);
        }
        u64 d0 = dup2(ma.x), d1 = dup2(ma.y), d2 = dup2(ma.z), d3 = dup2(ma.w);
        u64 d4 = dup2(mb.x), d5 = dup2(mb.y), d6 = dup2(mb.z), d7 = dup2(mb.w);
        FMA2(acc[0][0], d0, xv0); FMA2(acc[0][1], d0, xv1);
        FMA2(acc[1][0], d1, xv0); FMA2(acc[1][1], d1, xv1);
        FMA2(acc[2][0], d2, xv0); FMA2(acc[2][1], d2, xv1);
        FMA2(acc[3][0], d3, xv0); FMA2(acc[3][1], d3, xv1);
        FMA2(acc[4][0], d4, xv0); FMA2(acc[4][1], d4, xv1);
        FMA2(acc[5][0], d5, xv0); FMA2(acc[5][1], d5, xv1);
        FMA2(acc[6][0], d6, xv0); FMA2(acc[6][1], d6, xv1);
        FMA2(acc[7][0], d7, xv0); FMA2(acc[7][1], d7, xv1);
        xv0 = nx0; xv1 = nx1; ma = na; mb = nb;
    }
    #pragma unroll
    for (int i = 0; i < 8; i++) {
        float* orow = out + ((size_t)b * 128 + r0 + i) * NPIX + n0;
        *(u64*)(orow + 2 * lane)      = acc[i][0];
        *(u64*)(orow + 64 + 2 * lane) = acc[i][1];
    }
}

// ==================== launch ====================
extern "C" void kernel_launch(void* const* d_in, const int* in_sizes, int n_in,
                              void* d_out, int out_size)
{
    const float* x     = (const float*)d_in[0];
    const float* wqkv1 = (const float*)d_in[1];
    const float* wqkv2 = (const float*)d_in[2];
    const float* wdw1  = (const float*)d_in[3];
    const float* wdw2  = (const float*)d_in[4];
    const float* wpo1  = (const float*)d_in[5];
    const float* wpo2  = (const float*)d_in[6];
    const float* t1    = (const float*)d_in[7];
    const float* t2    = (const float*)d_in[8];
    float* out = (float*)d_out;

    cudaFuncSetAttribute(k1_qkv, cudaFuncAttributeMaxDynamicSharedMemorySize, SMEM_K1);
    cudaFuncSetAttribute(k4_out, cudaFuncAttributeMaxDynamicSharedMemorySize, SMEM_K4);

    k1_qkv<<<dim3(256, 8), 256, SMEM_K1>>>(x, wqkv1, wqkv2, wdw1, wdw2);
    k1b_reduce<<<20, 256>>>();
    k2_attn<<<1, 512>>>(wpo1, wpo2, t1, t2);
    k4_out<<<dim3(512, 4), 512, SMEM_K4>>>(out);
}